// round 4
// baseline (speedup 1.0000x reference)
#include <cuda_runtime.h>
#include <cuda_fp16.h>
#include <mma.h>
#include <cstdint>

using namespace nvcuda;

// ---------------------------------------------------------------------------
// LinearRNN via two-stage chunked factorization (L=16, K=64 truncation).
//   Stage 1: chunk-start states  Xs[c] = sum_{m<64} (A^m B) u[16c-1-m]  (+x0 fix)
//   Stage 2: Y[c, 64*dt+p] = sum_{s<=dt} H'_{dt-s} u[16c+s] + (C A^dt) Xs[c]
//            one block-lower-triangular GEMM  [NC x 1088] @ [1088 x 1024]
// Setup flattened to 2 launches: binary powers (1 block) + per-q derivation
// (64 independent blocks; powers of A commute so A^q = prod A^(2^i)).
// Baseline wmma (HMMA) + cp.async only (compute_103 virtual arch).
// ---------------------------------------------------------------------------

#define LCH 16
#define KTAP 64

// ------------------------- static device scratch ---------------------------
__device__ float  g_bp[6 * 4096];           // A^(2^i), i=0..5
__device__ float  g_xfix[4 * 64];           // A^{16c} x0
__device__ __half g_Wx[4096 * 64];          // stage-1 weights
__device__ __half g_Wy[1088 * 1024];        // stage-2 weights
__device__ __half g_Xs[16384 * 64];         // chunk-start states
__device__ __half g_u16[262144 * 64];       // u in fp16

// ------------------------------ helpers ------------------------------------
__device__ __forceinline__ uint32_t smem_addr(const void* p) {
    return (uint32_t)__cvta_generic_to_shared(p);
}
#define CP16(dst, src) \
    asm volatile("cp.async.cg.shared.global [%0], [%1], 16;" :: "r"(dst), "l"(src))
#define CP_COMMIT() asm volatile("cp.async.commit_group;" ::: "memory")
#define CP_WAIT1()  asm volatile("cp.async.wait_group 1;" ::: "memory")
#define CP_WAIT0()  asm volatile("cp.async.wait_group 0;" ::: "memory")

// acc += Sa(64x64) @ Sb(64x64), thread owns 4x4 tile at (r0, c0).
__device__ __forceinline__ void mm_acc(const float* Sa, const float* Sb, int tid,
                                       float acc[4][4]) {
    int r0 = (tid >> 4) << 2, c0 = (tid & 15) << 2;
    for (int k = 0; k < 64; k++) {
        float4 b = *(const float4*)&Sb[k * 64 + c0];
#pragma unroll
        for (int i = 0; i < 4; i++) {
            float a = Sa[(r0 + i) * 64 + k];
            acc[i][0] += a * b.x; acc[i][1] += a * b.y;
            acc[i][2] += a * b.z; acc[i][3] += a * b.w;
        }
    }
}

// ------------------------------ setup --------------------------------------
__global__ void prepass_u16(const float* __restrict__ u) {
    int idx = (blockIdx.x * 256 + threadIdx.x) * 8;
    float4 a = *(const float4*)(u + idx);
    float4 b = *(const float4*)(u + idx + 4);
    __half2 h0 = __floats2half2_rn(a.x, a.y), h1 = __floats2half2_rn(a.z, a.w);
    __half2 h2 = __floats2half2_rn(b.x, b.y), h3 = __floats2half2_rn(b.z, b.w);
    uint4 pk;
    pk.x = *(uint32_t*)&h0; pk.y = *(uint32_t*)&h1;
    pk.z = *(uint32_t*)&h2; pk.w = *(uint32_t*)&h3;
    *(uint4*)(g_u16 + idx) = pk;
}

// One block: A^(2^i) by repeated squaring in smem.
__global__ __launch_bounds__(256) void setup_binpow(const float* __restrict__ A) {
    __shared__ float Sa[4096], Sb[4096];
    int tid = threadIdx.x;
    int r0 = (tid >> 4) << 2, c0 = (tid & 15) << 2;
    for (int k = tid; k < 4096; k += 256) { float v = A[k]; Sa[k] = v; g_bp[k] = v; }
    __syncthreads();
    float* cur = Sa; float* nxt = Sb;
    for (int lvl = 1; lvl < 6; lvl++) {
        float acc[4][4] = {};
        mm_acc(cur, cur, tid, acc);
#pragma unroll
        for (int i = 0; i < 4; i++)
#pragma unroll
            for (int j = 0; j < 4; j++) {
                nxt[(r0 + i) * 64 + c0 + j] = acc[i][j];
                g_bp[lvl * 4096 + (r0 + i) * 64 + c0 + j] = acc[i][j];
            }
        __syncthreads();
        float* t = cur; cur = nxt; nxt = t;
    }
}

// Block q (0..63): P_q = prod_{bits} A^(2^i) (commuting), then all weights
// depending on q: Wx slot 63-q, Hp_{q+1} scatter, G_q, D diag, zeros, xfix.
__global__ __launch_bounds__(256) void setup_powers(const float* __restrict__ Bm,
                                                    const float* __restrict__ Cm,
                                                    const float* __restrict__ Dm,
                                                    const float* __restrict__ x0) {
    __shared__ float S0[4096], S1[4096], Sf[4096];
    const int q = blockIdx.x, tid = threadIdx.x;
    const int r0 = (tid >> 4) << 2, c0 = (tid & 15) << 2;
    float* Sr = S0; float* Sp = S1;

    for (int k = tid; k < 4096; k += 256)
        Sr[k] = ((k >> 6) == (k & 63)) ? 1.0f : 0.0f;
    for (int i = 0; i < 6; i++) {
        if (!(q & (1 << i))) continue;
        for (int k = tid; k < 4096; k += 256) Sf[k] = g_bp[i * 4096 + k];
        __syncthreads();
        float acc[4][4] = {};
        mm_acc(Sr, Sf, tid, acc);
#pragma unroll
        for (int i2 = 0; i2 < 4; i2++)
#pragma unroll
            for (int j = 0; j < 4; j++) Sp[(r0 + i2) * 64 + c0 + j] = acc[i2][j];
        __syncthreads();
        float* t = Sr; Sr = Sp; Sp = t;
    }
    // Mx_q = P_q @ B  -> Sp
    for (int k = tid; k < 4096; k += 256) Sf[k] = Bm[k];
    __syncthreads();
    {
        float acc[4][4] = {};
        mm_acc(Sr, Sf, tid, acc);
#pragma unroll
        for (int i2 = 0; i2 < 4; i2++)
#pragma unroll
            for (int j = 0; j < 4; j++) Sp[(r0 + i2) * 64 + c0 + j] = acc[i2][j];
    }
    __syncthreads();
    // Wx slot 63-q: Wx[(63-q)*64 + j][n] = Mx_q[n][j]
    for (int idx = tid; idx < 4096; idx += 256) {
        int j = idx >> 6, n = idx & 63;
        g_Wx[(size_t)((63 - q) * 64 + j) * 64 + n] = __float2half_rn(Sp[n * 64 + j]);
    }
    // load C (read-only for both matmuls below)
    for (int k = tid; k < 4096; k += 256) Sf[k] = Cm[k];
    __syncthreads();
    if (q < 15) {  // Hp_{q+1} = C @ Mx_q, scatter to pairs (s, s+q+1)
        float acc[4][4] = {};
        mm_acc(Sf, Sp, tid, acc);
        int m = q + 1;
        for (int s = 0; s + m < 16; s++) {
            int dt = s + m;
#pragma unroll
            for (int i2 = 0; i2 < 4; i2++)
#pragma unroll
                for (int j = 0; j < 4; j++)
                    g_Wy[(size_t)(64 * s + c0 + j) * 1024 + 64 * dt + r0 + i2] =
                        __float2half_rn(acc[i2][j]);
        }
    }
    if (q < 16) {  // G_q = C @ P_q  (Xs rows), and D on diagonal (s=dt=q)
        float acc[4][4] = {};
        mm_acc(Sf, Sr, tid, acc);
#pragma unroll
        for (int i2 = 0; i2 < 4; i2++)
#pragma unroll
            for (int j = 0; j < 4; j++)
                g_Wy[(size_t)(1024 + c0 + j) * 1024 + 64 * q + r0 + i2] =
                    __float2half_rn(acc[i2][j]);
        for (int idx = tid; idx < 4096; idx += 256) {
            int p = idx >> 6, j = idx & 63;
            g_Wy[(size_t)(64 * q + j) * 1024 + 64 * q + p] = __float2half_rn(Dm[idx]);
        }
    }
    // zero blocks with dt < s (120 pairs, strided over 64 blocks)
    for (int z = q; z < 120; z += 64) {
        int s = 1;
        while ((s * (s + 1)) / 2 <= z) s++;
        int dt = z - (s * (s - 1)) / 2;
        for (int idx = tid; idx < 4096; idx += 256) {
            int j = idx >> 6, p = idx & 63;
            g_Wy[(size_t)(64 * s + j) * 1024 + 64 * dt + p] = __half(0.0f);
        }
    }
    // xfix[c] = A^{16c} x0
    if ((q & 15) == 0 && tid < 64) {
        int c = q >> 4;
        float accx = 0.0f;
        for (int k = 0; k < 64; k++) accx += Sr[tid * 64 + k] * x0[k];
        g_xfix[c * 64 + tid] = accx;
    }
}

// ------------------------------ stage 1 ------------------------------------
__global__ __launch_bounds__(256)
void stage1(int NC) {
    extern __shared__ __half smh[];
    __half* As[2] = { smh, smh + 9216 };                 // [128][72]
    __half* Bs[2] = { smh + 18432, smh + 18432 + 4608 }; // [64][72]
    const int tid = threadIdx.x;
    const int c0 = blockIdx.x * 128;
    const uint4 zero4 = make_uint4(0, 0, 0, 0);

    auto load = [&](int bf, int q) {
        for (int idx = tid; idx < 1024; idx += 256) {
            int i = idx >> 3, cc = idx & 7;
            int t = 16 * (c0 + i) - KTAP + q;
            __half* d = As[bf] + i * 72 + cc * 8;
            if (t < 0) *(uint4*)d = zero4;
            else CP16(smem_addr(d), g_u16 + (size_t)t * 64 + cc * 8);
        }
        for (int idx = tid; idx < 512; idx += 256) {
            int j = idx >> 3, cc = idx & 7;
            CP16(smem_addr(Bs[bf] + j * 72 + cc * 8),
                 g_Wx + (size_t)(q * 64 + j) * 64 + cc * 8);
        }
        CP_COMMIT();
    };

    const int w = tid >> 5;
    wmma::fragment<wmma::accumulator, 16, 16, 16, float> acc[4];
#pragma unroll
    for (int n = 0; n < 4; n++) wmma::fill_fragment(acc[n], 0.0f);

    load(0, 0);
    for (int it = 0; it < KTAP; it++) {
        if (it + 1 < KTAP) { load((it + 1) & 1, it + 1); CP_WAIT1(); }
        else CP_WAIT0();
        __syncthreads();
        const __half* Ab = As[it & 1];
        const __half* Bb = Bs[it & 1];
#pragma unroll
        for (int kk = 0; kk < 4; kk++) {
            wmma::fragment<wmma::matrix_a, 16, 16, 16, __half, wmma::row_major> fa;
            wmma::load_matrix_sync(fa, Ab + (w * 16) * 72 + kk * 16, 72);
#pragma unroll
            for (int n = 0; n < 4; n++) {
                wmma::fragment<wmma::matrix_b, 16, 16, 16, __half, wmma::row_major> fb;
                wmma::load_matrix_sync(fb, Bb + (kk * 16) * 72 + n * 16, 72);
                wmma::mma_sync(acc[n], fa, fb, acc[n]);
            }
        }
        __syncthreads();
    }

    float* smf = reinterpret_cast<float*>(smh);
#pragma unroll
    for (int n = 0; n < 4; n++)
        wmma::store_matrix_sync(smf + (w * 16) * 64 + n * 16, acc[n], 64,
                                wmma::mem_row_major);
    __syncthreads();
    for (int idx = tid; idx < 8192; idx += 256) {
        int i = idx >> 6, n = idx & 63;
        int c = c0 + i;
        float v = smf[idx];
        if (c < 4) v += g_xfix[c * 64 + n];
        g_Xs[(size_t)c * 64 + n] = __float2half_rn(v);
    }
}

// ------------------------------ stage 2 ------------------------------------
// Triangular: CTA at col-tile nt (dt in {2nt,2nt+1}) needs k-tiles s<=2nt+1
// plus the Xs tile. nt is the fast blockIdx dim -> waves mix short/long CTAs.
__global__ __launch_bounds__(256)
void stage2(float* __restrict__ y, int NC) {
    extern __shared__ __half smh[];
    __half* As[2] = { smh, smh + 9216 };                  // [128][72]
    __half* Bs[2] = { smh + 18432, smh + 18432 + 8704 };  // [64][136]
    const int tid = threadIdx.x;
    const int mt = blockIdx.x >> 3, nt = blockIdx.x & 7;
    const int c0 = mt * 128, ncol0 = nt * 128;
    const int kmax = (2 * nt + 2 < 16) ? 2 * nt + 2 : 16;
    const int niter = kmax + 1;

    auto load = [&](int bf, int kt) {
        for (int idx = tid; idx < 1024; idx += 256) {
            int i = idx >> 3, cc = idx & 7;
            const __half* src = (kt < 16)
                ? g_u16 + (size_t)(c0 + i) * 1024 + kt * 64 + cc * 8
                : g_Xs + (size_t)(c0 + i) * 64 + cc * 8;
            CP16(smem_addr(As[bf] + i * 72 + cc * 8), src);
        }
        for (int idx = tid; idx < 1024; idx += 256) {
            int r = idx >> 4, cc = idx & 15;
            CP16(smem_addr(Bs[bf] + r * 136 + cc * 8),
                 g_Wy + (size_t)(kt * 64 + r) * 1024 + ncol0 + cc * 8);
        }
        CP_COMMIT();
    };

    const int w = tid >> 5;
    const int wr = w >> 1, wc = w & 1;
    wmma::fragment<wmma::accumulator, 16, 16, 16, float> acc[2][4];
#pragma unroll
    for (int tr = 0; tr < 2; tr++)
#pragma unroll
        for (int n = 0; n < 4; n++) wmma::fill_fragment(acc[tr][n], 0.0f);

    load(0, 0);
    for (int it = 0; it < niter; it++) {
        if (it + 1 < niter) {
            int ktn = (it + 1 == niter - 1) ? 16 : it + 1;
            load((it + 1) & 1, ktn);
            CP_WAIT1();
        } else CP_WAIT0();
        __syncthreads();
        const __half* Ab = As[it & 1];
        const __half* Bb = Bs[it & 1];
#pragma unroll
        for (int kk = 0; kk < 4; kk++) {
            wmma::fragment<wmma::matrix_b, 16, 16, 16, __half, wmma::row_major> fb[4];
#pragma unroll
            for (int n = 0; n < 4; n++)
                wmma::load_matrix_sync(fb[n], Bb + (kk * 16) * 136 + wc * 64 + n * 16, 136);
#pragma unroll
            for (int tr = 0; tr < 2; tr++) {
                wmma::fragment<wmma::matrix_a, 16, 16, 16, __half, wmma::row_major> fa;
                wmma::load_matrix_sync(fa, Ab + (wr * 32 + tr * 16) * 72 + kk * 16, 72);
#pragma unroll
                for (int n = 0; n < 4; n++)
                    wmma::mma_sync(acc[tr][n], fa, fb[n], acc[tr][n]);
            }
        }
        __syncthreads();
    }

#pragma unroll
    for (int tr = 0; tr < 2; tr++)
#pragma unroll
        for (int n = 0; n < 4; n++)
            wmma::store_matrix_sync(
                y + (size_t)(c0 + wr * 32 + tr * 16) * 1024 + ncol0 + wc * 64 + n * 16,
                acc[tr][n], 1024, wmma::mem_row_major);
}

// ---------------------------------------------------------------------------
extern "C" void kernel_launch(void* const* d_in, const int* in_sizes, int n_in,
                              void* d_out, int out_size) {
    const float* u  = (const float*)d_in[0];
    const float* x0 = (const float*)d_in[1];
    const float* A  = (const float*)d_in[2];
    const float* B  = (const float*)d_in[3];
    const float* C  = (const float*)d_in[4];
    const float* D  = (const float*)d_in[5];
    float* y = (float*)d_out;

    const int T  = in_sizes[0] / 64;     // 262144
    const int NC = T / LCH;              // 16384

    static bool attr_set = false;
    if (!attr_set) {
        cudaFuncSetAttribute(stage1, cudaFuncAttributeMaxDynamicSharedMemorySize, 55296);
        cudaFuncSetAttribute(stage2, cudaFuncAttributeMaxDynamicSharedMemorySize, 71680);
        attr_set = true;
    }

    prepass_u16<<<T * 64 / 2048, 256>>>(u);
    setup_binpow<<<1, 256>>>(A);
    setup_powers<<<64, 256>>>(B, C, D, x0);

    stage1<<<NC / 128, 256, 55296>>>(NC);
    stage2<<<(NC / 128) * 8, 256, 71680>>>(y, NC);
}

// round 5
// speedup vs baseline: 1.7539x; 1.7539x over previous
#include <cuda_runtime.h>
#include <cuda_fp16.h>
#include <mma.h>
#include <cstdint>

using namespace nvcuda;

// ---------------------------------------------------------------------------
// LinearRNN via two-stage chunked factorization (L=16, K=64 truncation).
//   Z  = Uc[16384x1024] @ Wf[1024x256]      (dense contiguous GEMM)
//   Xs[c] = sum_b Z[c-4+b, 64b:64b+64] (+ A^{16c} x0 for c<4)
//   Y  = [Uc | Xs][16384x1088] @ Wy[1088x1024]  (block-lower-triangular)
// Both GEMMs: 128x128 CTA, 8 warps in 2x4 grid, 64x32 warp tiles (MMA-bound),
// cp.async double buffering, 2 CTAs/SM. Baseline wmma only (compute_103).
// ---------------------------------------------------------------------------

// ------------------------- static device scratch ---------------------------
__device__ float  g_bp[6 * 4096];           // A^(2^i), i=0..5
__device__ float  g_xfix[4 * 64];           // A^{16c} x0
__device__ __half g_Wf[1024 * 256];         // stage-1 weights (Z GEMM)
__device__ __half g_Wy[1088 * 1024];        // stage-2 weights
__device__ float  g_Z [16384 * 256];        // stage-1 partial states
__device__ __half g_Xs[16384 * 64];         // chunk-start states
__device__ __half g_u16[262144 * 64];       // u in fp16 (= Uc[16384][1024])

// ------------------------------ helpers ------------------------------------
__device__ __forceinline__ uint32_t smem_addr(const void* p) {
    return (uint32_t)__cvta_generic_to_shared(p);
}
#define CP16(dst, src) \
    asm volatile("cp.async.cg.shared.global [%0], [%1], 16;" :: "r"(dst), "l"(src))
#define CP_COMMIT() asm volatile("cp.async.commit_group;" ::: "memory")
#define CP_WAIT1()  asm volatile("cp.async.wait_group 1;" ::: "memory")
#define CP_WAIT0()  asm volatile("cp.async.wait_group 0;" ::: "memory")

__device__ __forceinline__ void mm_acc(const float* Sa, const float* Sb, int tid,
                                       float acc[4][4]) {
    int r0 = (tid >> 4) << 2, c0 = (tid & 15) << 2;
    for (int k = 0; k < 64; k++) {
        float4 b = *(const float4*)&Sb[k * 64 + c0];
#pragma unroll
        for (int i = 0; i < 4; i++) {
            float a = Sa[(r0 + i) * 64 + k];
            acc[i][0] += a * b.x; acc[i][1] += a * b.y;
            acc[i][2] += a * b.z; acc[i][3] += a * b.w;
        }
    }
}

// ------------------------------ setup --------------------------------------
__global__ void prepass_u16(const float* __restrict__ u) {
    int idx = (blockIdx.x * 256 + threadIdx.x) * 8;
    float4 a = *(const float4*)(u + idx);
    float4 b = *(const float4*)(u + idx + 4);
    __half2 h0 = __floats2half2_rn(a.x, a.y), h1 = __floats2half2_rn(a.z, a.w);
    __half2 h2 = __floats2half2_rn(b.x, b.y), h3 = __floats2half2_rn(b.z, b.w);
    uint4 pk;
    pk.x = *(uint32_t*)&h0; pk.y = *(uint32_t*)&h1;
    pk.z = *(uint32_t*)&h2; pk.w = *(uint32_t*)&h3;
    *(uint4*)(g_u16 + idx) = pk;
}

__global__ __launch_bounds__(256) void setup_binpow(const float* __restrict__ A) {
    __shared__ float Sa[4096], Sb[4096];
    int tid = threadIdx.x;
    int r0 = (tid >> 4) << 2, c0 = (tid & 15) << 2;
    for (int k = tid; k < 4096; k += 256) { float v = A[k]; Sa[k] = v; g_bp[k] = v; }
    __syncthreads();
    float* cur = Sa; float* nxt = Sb;
    for (int lvl = 1; lvl < 6; lvl++) {
        float acc[4][4] = {};
        mm_acc(cur, cur, tid, acc);
#pragma unroll
        for (int i = 0; i < 4; i++)
#pragma unroll
            for (int j = 0; j < 4; j++) {
                nxt[(r0 + i) * 64 + c0 + j] = acc[i][j];
                g_bp[lvl * 4096 + (r0 + i) * 64 + c0 + j] = acc[i][j];
            }
        __syncthreads();
        float* t = cur; cur = nxt; nxt = t;
    }
}

// Block q (0..63): P_q = prod_bits A^(2^i); derive Wf slot, Hp_{q+1} scatter,
// G_q, D diag, triangular zeros, xfix.
__global__ __launch_bounds__(256) void setup_powers(const float* __restrict__ Bm,
                                                    const float* __restrict__ Cm,
                                                    const float* __restrict__ Dm,
                                                    const float* __restrict__ x0) {
    __shared__ float S0[4096], S1[4096], Sf[4096];
    const int q = blockIdx.x, tid = threadIdx.x;
    const int r0 = (tid >> 4) << 2, c0 = (tid & 15) << 2;
    float* Sr = S0; float* Sp = S1;

    for (int k = tid; k < 4096; k += 256)
        Sr[k] = ((k >> 6) == (k & 63)) ? 1.0f : 0.0f;
    for (int i = 0; i < 6; i++) {
        if (!(q & (1 << i))) continue;
        for (int k = tid; k < 4096; k += 256) Sf[k] = g_bp[i * 4096 + k];
        __syncthreads();
        float acc[4][4] = {};
        mm_acc(Sr, Sf, tid, acc);
#pragma unroll
        for (int i2 = 0; i2 < 4; i2++)
#pragma unroll
            for (int j = 0; j < 4; j++) Sp[(r0 + i2) * 64 + c0 + j] = acc[i2][j];
        __syncthreads();
        float* t = Sr; Sr = Sp; Sp = t;
    }
    // Mx_q = P_q @ B -> Sp
    for (int k = tid; k < 4096; k += 256) Sf[k] = Bm[k];
    __syncthreads();
    {
        float acc[4][4] = {};
        mm_acc(Sr, Sf, tid, acc);
#pragma unroll
        for (int i2 = 0; i2 < 4; i2++)
#pragma unroll
            for (int j = 0; j < 4; j++) Sp[(r0 + i2) * 64 + c0 + j] = acc[i2][j];
    }
    __syncthreads();
    // Wf slot: q = 63-16b-r  ->  b=(63-q)>>4, r=(63-q)&15
    // Wf[64r+j][64b+n] = Mx_q[n][j]
    {
        int bb = (63 - q) >> 4, rr = (63 - q) & 15;
        for (int idx = tid; idx < 4096; idx += 256) {
            int j = idx >> 6, n = idx & 63;
            g_Wf[(size_t)(64 * rr + j) * 256 + 64 * bb + n] =
                __float2half_rn(Sp[n * 64 + j]);
        }
    }
    for (int k = tid; k < 4096; k += 256) Sf[k] = Cm[k];
    __syncthreads();
    if (q < 15) {  // Hp_{q+1} = C @ Mx_q, scatter to (s, s+q+1)
        float acc[4][4] = {};
        mm_acc(Sf, Sp, tid, acc);
        int m = q + 1;
        for (int s = 0; s + m < 16; s++) {
            int dt = s + m;
#pragma unroll
            for (int i2 = 0; i2 < 4; i2++)
#pragma unroll
                for (int j = 0; j < 4; j++)
                    g_Wy[(size_t)(64 * s + c0 + j) * 1024 + 64 * dt + r0 + i2] =
                        __float2half_rn(acc[i2][j]);
        }
    }
    if (q < 16) {  // G_q = C @ P_q (Xs rows) and D on diagonal
        float acc[4][4] = {};
        mm_acc(Sf, Sr, tid, acc);
#pragma unroll
        for (int i2 = 0; i2 < 4; i2++)
#pragma unroll
            for (int j = 0; j < 4; j++)
                g_Wy[(size_t)(1024 + c0 + j) * 1024 + 64 * q + r0 + i2] =
                    __float2half_rn(acc[i2][j]);
        for (int idx = tid; idx < 4096; idx += 256) {
            int p = idx >> 6, j = idx & 63;
            g_Wy[(size_t)(64 * q + j) * 1024 + 64 * q + p] = __float2half_rn(Dm[idx]);
        }
    }
    // zeros for dt < s
    for (int z = q; z < 120; z += 64) {
        int s = 1;
        while ((s * (s + 1)) / 2 <= z) s++;
        int dt = z - (s * (s - 1)) / 2;
        for (int idx = tid; idx < 4096; idx += 256) {
            int j = idx >> 6, p = idx & 63;
            g_Wy[(size_t)(64 * s + j) * 1024 + 64 * dt + p] = __half(0.0f);
        }
    }
    if ((q & 15) == 0 && tid < 64) {
        int c = q >> 4;
        float accx = 0.0f;
        for (int k = 0; k < 64; k++) accx += Sr[tid * 64 + k] * x0[k];
        g_xfix[c * 64 + tid] = accx;
    }
}

// ------------------------- stage 1 GEMM: Z = Uc @ Wf ------------------------
// CTA 128x128 (of N=256), 8 warps 2x4, warp tile 64x32, K=1024 (16 iters).
__global__ __launch_bounds__(256, 2)
void gemm1() {
    extern __shared__ __half smh[];
    __half* As[2] = { smh, smh + 9216 };                  // [128][72]
    __half* Bs[2] = { smh + 18432, smh + 18432 + 8704 };  // [64][136]
    const int tid = threadIdx.x;
    const int mt = blockIdx.x >> 1, nt = blockIdx.x & 1;
    const int c0 = mt * 128, ncol0 = nt * 128;

    auto load = [&](int bf, int kt) {
        for (int idx = tid; idx < 1024; idx += 256) {
            int i = idx >> 3, cc = (idx & 7) << 3;
            CP16(smem_addr(As[bf] + i * 72 + cc),
                 g_u16 + (size_t)(c0 + i) * 1024 + kt * 64 + cc);
        }
        for (int idx = tid; idx < 1024; idx += 256) {
            int r = idx >> 4, cc = (idx & 15) << 3;
            CP16(smem_addr(Bs[bf] + r * 136 + cc),
                 g_Wf + (size_t)(kt * 64 + r) * 256 + ncol0 + cc);
        }
        CP_COMMIT();
    };

    const int w = tid >> 5;
    const int wr = w >> 2, wc = w & 3;                    // 2x4 warp grid
    wmma::fragment<wmma::accumulator, 16, 16, 16, float> acc[4][2];
#pragma unroll
    for (int tr = 0; tr < 4; tr++)
#pragma unroll
        for (int n = 0; n < 2; n++) wmma::fill_fragment(acc[tr][n], 0.0f);

    load(0, 0);
    for (int it = 0; it < 16; it++) {
        if (it + 1 < 16) { load((it + 1) & 1, it + 1); CP_WAIT1(); }
        else CP_WAIT0();
        __syncthreads();
        const __half* Ab = As[it & 1];
        const __half* Bb = Bs[it & 1];
#pragma unroll
        for (int kk = 0; kk < 4; kk++) {
            wmma::fragment<wmma::matrix_b, 16, 16, 16, __half, wmma::row_major> fb[2];
#pragma unroll
            for (int n = 0; n < 2; n++)
                wmma::load_matrix_sync(fb[n], Bb + (kk * 16) * 136 + wc * 32 + n * 16, 136);
#pragma unroll
            for (int tr = 0; tr < 4; tr++) {
                wmma::fragment<wmma::matrix_a, 16, 16, 16, __half, wmma::row_major> fa;
                wmma::load_matrix_sync(fa, Ab + (wr * 64 + tr * 16) * 72 + kk * 16, 72);
#pragma unroll
                for (int n = 0; n < 2; n++)
                    wmma::mma_sync(acc[tr][n], fa, fb[n], acc[tr][n]);
            }
        }
        __syncthreads();
    }

#pragma unroll
    for (int tr = 0; tr < 4; tr++)
#pragma unroll
        for (int n = 0; n < 2; n++)
            wmma::store_matrix_sync(
                g_Z + (size_t)(c0 + wr * 64 + tr * 16) * 256 + ncol0 + wc * 32 + n * 16,
                acc[tr][n], 256, wmma::mem_row_major);
}

// ---------------------- stage-1 epilogue: Xs from Z ------------------------
__global__ void xs_epi() {
    int idx = blockIdx.x * 256 + threadIdx.x;   // over 16384*64
    int c = idx >> 6, n = idx & 63;
    float v = (c < 4) ? g_xfix[c * 64 + n] : 0.0f;
#pragma unroll
    for (int b = 0; b < 4; b++) {
        int cp = c - 4 + b;
        if (cp >= 0) v += g_Z[(size_t)cp * 256 + 64 * b + n];
    }
    g_Xs[idx] = __float2half_rn(v);
}

// ------------------------------ stage 2 ------------------------------------
// Triangular: col-tile nt needs k-tiles s <= 2nt+1 plus Xs tile.
__global__ __launch_bounds__(256, 2)
void stage2(float* __restrict__ y) {
    extern __shared__ __half smh[];
    __half* As[2] = { smh, smh + 9216 };                  // [128][72]
    __half* Bs[2] = { smh + 18432, smh + 18432 + 8704 };  // [64][136]
    const int tid = threadIdx.x;
    const int mt = blockIdx.x >> 3, nt = blockIdx.x & 7;
    const int c0 = mt * 128, ncol0 = nt * 128;
    const int kmax = (2 * nt + 2 < 16) ? 2 * nt + 2 : 16;
    const int niter = kmax + 1;

    auto load = [&](int bf, int kt) {
        for (int idx = tid; idx < 1024; idx += 256) {
            int i = idx >> 3, cc = (idx & 7) << 3;
            const __half* src = (kt < 16)
                ? g_u16 + (size_t)(c0 + i) * 1024 + kt * 64 + cc
                : g_Xs + (size_t)(c0 + i) * 64 + cc;
            CP16(smem_addr(As[bf] + i * 72 + cc), src);
        }
        for (int idx = tid; idx < 1024; idx += 256) {
            int r = idx >> 4, cc = (idx & 15) << 3;
            CP16(smem_addr(Bs[bf] + r * 136 + cc),
                 g_Wy + (size_t)(kt * 64 + r) * 1024 + ncol0 + cc);
        }
        CP_COMMIT();
    };

    const int w = tid >> 5;
    const int wr = w >> 2, wc = w & 3;                    // 2x4 warp grid
    wmma::fragment<wmma::accumulator, 16, 16, 16, float> acc[4][2];
#pragma unroll
    for (int tr = 0; tr < 4; tr++)
#pragma unroll
        for (int n = 0; n < 2; n++) wmma::fill_fragment(acc[tr][n], 0.0f);

    load(0, 0);
    for (int it = 0; it < niter; it++) {
        if (it + 1 < niter) {
            int ktn = (it + 1 == niter - 1) ? 16 : it + 1;
            load((it + 1) & 1, ktn);
            CP_WAIT1();
        } else CP_WAIT0();
        __syncthreads();
        const __half* Ab = As[it & 1];
        const __half* Bb = Bs[it & 1];
#pragma unroll
        for (int kk = 0; kk < 4; kk++) {
            wmma::fragment<wmma::matrix_b, 16, 16, 16, __half, wmma::row_major> fb[2];
#pragma unroll
            for (int n = 0; n < 2; n++)
                wmma::load_matrix_sync(fb[n], Bb + (kk * 16) * 136 + wc * 32 + n * 16, 136);
#pragma unroll
            for (int tr = 0; tr < 4; tr++) {
                wmma::fragment<wmma::matrix_a, 16, 16, 16, __half, wmma::row_major> fa;
                wmma::load_matrix_sync(fa, Ab + (wr * 64 + tr * 16) * 72 + kk * 16, 72);
#pragma unroll
                for (int n = 0; n < 2; n++)
                    wmma::mma_sync(acc[tr][n], fa, fb[n], acc[tr][n]);
            }
        }
        __syncthreads();
    }

#pragma unroll
    for (int tr = 0; tr < 4; tr++)
#pragma unroll
        for (int n = 0; n < 2; n++)
            wmma::store_matrix_sync(
                y + (size_t)(c0 + wr * 64 + tr * 16) * 1024 + ncol0 + wc * 32 + n * 16,
                acc[tr][n], 1024, wmma::mem_row_major);
}

// ---------------------------------------------------------------------------
extern "C" void kernel_launch(void* const* d_in, const int* in_sizes, int n_in,
                              void* d_out, int out_size) {
    const float* u  = (const float*)d_in[0];
    const float* x0 = (const float*)d_in[1];
    const float* A  = (const float*)d_in[2];
    const float* B  = (const float*)d_in[3];
    const float* C  = (const float*)d_in[4];
    const float* D  = (const float*)d_in[5];
    float* y = (float*)d_out;

    const int T  = in_sizes[0] / 64;     // 262144
    const int NC = T / 16;               // 16384

    static bool attr_set = false;
    if (!attr_set) {
        cudaFuncSetAttribute(gemm1,  cudaFuncAttributeMaxDynamicSharedMemorySize, 71680);
        cudaFuncSetAttribute(stage2, cudaFuncAttributeMaxDynamicSharedMemorySize, 71680);
        attr_set = true;
    }

    prepass_u16<<<T * 64 / 2048, 256>>>(u);
    setup_binpow<<<1, 256>>>(A);
    setup_powers<<<64, 256>>>(B, C, D, x0);

    gemm1<<<(NC / 128) * 2, 256, 71680>>>();
    xs_epi<<<NC * 64 / 256, 256>>>();
    stage2<<<(NC / 128) * 8, 256, 71680>>>(y);
}

// round 6
// speedup vs baseline: 1.9997x; 1.1402x over previous
#include <cuda_runtime.h>
#include <cuda_fp16.h>
#include <mma.h>
#include <cstdint>

using namespace nvcuda;

// ---------------------------------------------------------------------------
// LinearRNN via two-stage chunked factorization (L=16, K=64 truncation).
//   Z  = Uc[16384x1024] @ Wf[1024x256]      (dense contiguous GEMM)
//   Xs[c] = sum_b Z[c-4+b, 64b:64b+64] (+ A^{16c} x0 for c<4)
//   Y  = [Uc | Xs][16384x1088] @ Wy[1088x1024]  (block-lower-triangular)
// GEMMs: 128x128 CTA, 8 warps 2x4, 64x32 warp tiles, 3-stage cp.async
// pipeline with ONE barrier per k-iter, 2 CTAs/SM. wmma only (compute_103).
// ---------------------------------------------------------------------------

#define STAGE_H 17920               // halves per pipeline stage (A 9216 + B 8704)
#define SMEM_3S (3 * STAGE_H * 2)   // 107520 bytes

// ------------------------- static device scratch ---------------------------
__device__ float  g_bp[6 * 4096];           // A^(2^i), i=0..5
__device__ float  g_xfix[4 * 64];           // A^{16c} x0
__device__ __half g_Wf[1024 * 256];         // stage-1 weights (Z GEMM)
__device__ __half g_Wy[1088 * 1024];        // stage-2 weights
__device__ float  g_Z [16384 * 256];        // stage-1 partial states
__device__ __half g_Xs[16384 * 64];         // chunk-start states
__device__ __half g_u16[262144 * 64];       // u in fp16 (= Uc[16384][1024])

// ------------------------------ helpers ------------------------------------
__device__ __forceinline__ uint32_t smem_addr(const void* p) {
    return (uint32_t)__cvta_generic_to_shared(p);
}
#define CP16(dst, src) \
    asm volatile("cp.async.cg.shared.global [%0], [%1], 16;" :: "r"(dst), "l"(src))
#define CP_COMMIT() asm volatile("cp.async.commit_group;" ::: "memory")
#define CP_WAIT1()  asm volatile("cp.async.wait_group 1;" ::: "memory")
#define CP_WAIT0()  asm volatile("cp.async.wait_group 0;" ::: "memory")

__device__ __forceinline__ void mm_acc(const float* Sa, const float* Sb, int tid,
                                       float acc[4][4]) {
    int r0 = (tid >> 4) << 2, c0 = (tid & 15) << 2;
    for (int k = 0; k < 64; k++) {
        float4 b = *(const float4*)&Sb[k * 64 + c0];
#pragma unroll
        for (int i = 0; i < 4; i++) {
            float a = Sa[(r0 + i) * 64 + k];
            acc[i][0] += a * b.x; acc[i][1] += a * b.y;
            acc[i][2] += a * b.z; acc[i][3] += a * b.w;
        }
    }
}

// --------------------- prepass + binary powers (fused) ----------------------
// Blocks 0..NB-1: convert u fp32->fp16. Block NB: A^(2^i) squaring chain
// (serial-latency work overlapped under the DRAM-bound conversion).
__global__ __launch_bounds__(256) void prepass_fused(const float* __restrict__ u,
                                                     const float* __restrict__ A,
                                                     int NB) {
    __shared__ float Sa[4096], Sb[4096];
    if ((int)blockIdx.x < NB) {
        int idx = (blockIdx.x * 256 + threadIdx.x) * 8;
        float4 a = *(const float4*)(u + idx);
        float4 b = *(const float4*)(u + idx + 4);
        __half2 h0 = __floats2half2_rn(a.x, a.y), h1 = __floats2half2_rn(a.z, a.w);
        __half2 h2 = __floats2half2_rn(b.x, b.y), h3 = __floats2half2_rn(b.z, b.w);
        uint4 pk;
        pk.x = *(uint32_t*)&h0; pk.y = *(uint32_t*)&h1;
        pk.z = *(uint32_t*)&h2; pk.w = *(uint32_t*)&h3;
        *(uint4*)(g_u16 + idx) = pk;
        return;
    }
    int tid = threadIdx.x;
    int r0 = (tid >> 4) << 2, c0 = (tid & 15) << 2;
    for (int k = tid; k < 4096; k += 256) { float v = A[k]; Sa[k] = v; g_bp[k] = v; }
    __syncthreads();
    float* cur = Sa; float* nxt = Sb;
    for (int lvl = 1; lvl < 6; lvl++) {
        float acc[4][4] = {};
        mm_acc(cur, cur, tid, acc);
#pragma unroll
        for (int i = 0; i < 4; i++)
#pragma unroll
            for (int j = 0; j < 4; j++) {
                nxt[(r0 + i) * 64 + c0 + j] = acc[i][j];
                g_bp[lvl * 4096 + (r0 + i) * 64 + c0 + j] = acc[i][j];
            }
        __syncthreads();
        float* t = cur; cur = nxt; nxt = t;
    }
}

// Block q (0..63): P_q = prod_bits A^(2^i); derive Wf slot, Hp_{q+1} scatter,
// G_q, D diag, triangular zeros, xfix.
__global__ __launch_bounds__(256) void setup_powers(const float* __restrict__ Bm,
                                                    const float* __restrict__ Cm,
                                                    const float* __restrict__ Dm,
                                                    const float* __restrict__ x0) {
    __shared__ float S0[4096], S1[4096], Sf[4096];
    const int q = blockIdx.x, tid = threadIdx.x;
    const int r0 = (tid >> 4) << 2, c0 = (tid & 15) << 2;
    float* Sr = S0; float* Sp = S1;

    for (int k = tid; k < 4096; k += 256)
        Sr[k] = ((k >> 6) == (k & 63)) ? 1.0f : 0.0f;
    for (int i = 0; i < 6; i++) {
        if (!(q & (1 << i))) continue;
        for (int k = tid; k < 4096; k += 256) Sf[k] = g_bp[i * 4096 + k];
        __syncthreads();
        float acc[4][4] = {};
        mm_acc(Sr, Sf, tid, acc);
#pragma unroll
        for (int i2 = 0; i2 < 4; i2++)
#pragma unroll
            for (int j = 0; j < 4; j++) Sp[(r0 + i2) * 64 + c0 + j] = acc[i2][j];
        __syncthreads();
        float* t = Sr; Sr = Sp; Sp = t;
    }
    // Mx_q = P_q @ B -> Sp
    for (int k = tid; k < 4096; k += 256) Sf[k] = Bm[k];
    __syncthreads();
    {
        float acc[4][4] = {};
        mm_acc(Sr, Sf, tid, acc);
#pragma unroll
        for (int i2 = 0; i2 < 4; i2++)
#pragma unroll
            for (int j = 0; j < 4; j++) Sp[(r0 + i2) * 64 + c0 + j] = acc[i2][j];
    }
    __syncthreads();
    // Wf slot: q = 63-16b-r  ->  b=(63-q)>>4, r=(63-q)&15
    {
        int bb = (63 - q) >> 4, rr = (63 - q) & 15;
        for (int idx = tid; idx < 4096; idx += 256) {
            int j = idx >> 6, n = idx & 63;
            g_Wf[(size_t)(64 * rr + j) * 256 + 64 * bb + n] =
                __float2half_rn(Sp[n * 64 + j]);
        }
    }
    for (int k = tid; k < 4096; k += 256) Sf[k] = Cm[k];
    __syncthreads();
    if (q < 15) {  // Hp_{q+1} = C @ Mx_q, scatter to (s, s+q+1)
        float acc[4][4] = {};
        mm_acc(Sf, Sp, tid, acc);
        int m = q + 1;
        for (int s = 0; s + m < 16; s++) {
            int dt = s + m;
#pragma unroll
            for (int i2 = 0; i2 < 4; i2++)
#pragma unroll
                for (int j = 0; j < 4; j++)
                    g_Wy[(size_t)(64 * s + c0 + j) * 1024 + 64 * dt + r0 + i2] =
                        __float2half_rn(acc[i2][j]);
        }
    }
    if (q < 16) {  // G_q = C @ P_q (Xs rows) and D on diagonal
        float acc[4][4] = {};
        mm_acc(Sf, Sr, tid, acc);
#pragma unroll
        for (int i2 = 0; i2 < 4; i2++)
#pragma unroll
            for (int j = 0; j < 4; j++)
                g_Wy[(size_t)(1024 + c0 + j) * 1024 + 64 * q + r0 + i2] =
                    __float2half_rn(acc[i2][j]);
        for (int idx = tid; idx < 4096; idx += 256) {
            int p = idx >> 6, j = idx & 63;
            g_Wy[(size_t)(64 * q + j) * 1024 + 64 * q + p] = __float2half_rn(Dm[idx]);
        }
    }
    // zeros for dt < s
    for (int z = q; z < 120; z += 64) {
        int s = 1;
        while ((s * (s + 1)) / 2 <= z) s++;
        int dt = z - (s * (s - 1)) / 2;
        for (int idx = tid; idx < 4096; idx += 256) {
            int j = idx >> 6, p = idx & 63;
            g_Wy[(size_t)(64 * s + j) * 1024 + 64 * dt + p] = __half(0.0f);
        }
    }
    if ((q & 15) == 0 && tid < 64) {
        int c = q >> 4;
        float accx = 0.0f;
        for (int k = 0; k < 64; k++) accx += Sr[tid * 64 + k] * x0[k];
        g_xfix[c * 64 + tid] = accx;
    }
}

// ------------------------- stage 1 GEMM: Z = Uc @ Wf ------------------------
__global__ __launch_bounds__(256, 2)
void gemm1() {
    extern __shared__ __half smh[];
    const int tid = threadIdx.x;
    const int mt = blockIdx.x >> 1, nt = blockIdx.x & 1;
    const int c0 = mt * 128, ncol0 = nt * 128;

    auto load = [&](int s, int kt) {
        __half* Ab = smh + s * STAGE_H;
        __half* Bb = smh + s * STAGE_H + 9216;
        for (int idx = tid; idx < 1024; idx += 256) {
            int i = idx >> 3, cc = (idx & 7) << 3;
            CP16(smem_addr(Ab + i * 72 + cc),
                 g_u16 + (size_t)(c0 + i) * 1024 + kt * 64 + cc);
        }
        for (int idx = tid; idx < 1024; idx += 256) {
            int r = idx >> 4, cc = (idx & 15) << 3;
            CP16(smem_addr(Bb + r * 136 + cc),
                 g_Wf + (size_t)(kt * 64 + r) * 256 + ncol0 + cc);
        }
        CP_COMMIT();
    };

    const int w = tid >> 5;
    const int wr = w >> 2, wc = w & 3;
    wmma::fragment<wmma::accumulator, 16, 16, 16, float> acc[4][2];
#pragma unroll
    for (int tr = 0; tr < 4; tr++)
#pragma unroll
        for (int n = 0; n < 2; n++) wmma::fill_fragment(acc[tr][n], 0.0f);

    load(0, 0);
    load(1, 1);
    int sidx = 0;
    for (int it = 0; it < 16; it++) {
        if (it + 1 < 16) CP_WAIT1(); else CP_WAIT0();
        __syncthreads();
        if (it + 2 < 16) load((sidx + 2) % 3, it + 2);
        const __half* Ab = smh + sidx * STAGE_H;
        const __half* Bb = smh + sidx * STAGE_H + 9216;
#pragma unroll
        for (int kk = 0; kk < 4; kk++) {
            wmma::fragment<wmma::matrix_b, 16, 16, 16, __half, wmma::row_major> fb[2];
#pragma unroll
            for (int n = 0; n < 2; n++)
                wmma::load_matrix_sync(fb[n], Bb + (kk * 16) * 136 + wc * 32 + n * 16, 136);
#pragma unroll
            for (int tr = 0; tr < 4; tr++) {
                wmma::fragment<wmma::matrix_a, 16, 16, 16, __half, wmma::row_major> fa;
                wmma::load_matrix_sync(fa, Ab + (wr * 64 + tr * 16) * 72 + kk * 16, 72);
#pragma unroll
                for (int n = 0; n < 2; n++)
                    wmma::mma_sync(acc[tr][n], fa, fb[n], acc[tr][n]);
            }
        }
        if (++sidx == 3) sidx = 0;
    }

#pragma unroll
    for (int tr = 0; tr < 4; tr++)
#pragma unroll
        for (int n = 0; n < 2; n++)
            wmma::store_matrix_sync(
                g_Z + (size_t)(c0 + wr * 64 + tr * 16) * 256 + ncol0 + wc * 32 + n * 16,
                acc[tr][n], 256, wmma::mem_row_major);
}

// ---------------------- stage-1 epilogue: Xs from Z ------------------------
__global__ void xs_epi() {
    int idx = blockIdx.x * 256 + threadIdx.x;
    int c = idx >> 6, n = idx & 63;
    float v = (c < 4) ? g_xfix[c * 64 + n] : 0.0f;
#pragma unroll
    for (int b = 0; b < 4; b++) {
        int cp = c - 4 + b;
        if (cp >= 0) v += g_Z[(size_t)cp * 256 + 64 * b + n];
    }
    g_Xs[idx] = __float2half_rn(v);
}

// ------------------------------ stage 2 ------------------------------------
__global__ __launch_bounds__(256, 2)
void stage2(float* __restrict__ y) {
    extern __shared__ __half smh[];
    const int tid = threadIdx.x;
    const int mt = blockIdx.x >> 3, nt = blockIdx.x & 7;
    const int c0 = mt * 128, ncol0 = nt * 128;
    const int kmax = (2 * nt + 2 < 16) ? 2 * nt + 2 : 16;
    const int niter = kmax + 1;

    auto load = [&](int s, int i2) {
        int kt = (i2 == niter - 1) ? 16 : i2;
        __half* Ab = smh + s * STAGE_H;
        __half* Bb = smh + s * STAGE_H + 9216;
        for (int idx = tid; idx < 1024; idx += 256) {
            int i = idx >> 3, cc = (idx & 7) << 3;
            const __half* src = (kt < 16)
                ? g_u16 + (size_t)(c0 + i) * 1024 + kt * 64 + cc
                : g_Xs + (size_t)(c0 + i) * 64 + cc;
            CP16(smem_addr(Ab + i * 72 + cc), src);
        }
        for (int idx = tid; idx < 1024; idx += 256) {
            int r = idx >> 4, cc = (idx & 15) << 3;
            CP16(smem_addr(Bb + r * 136 + cc),
                 g_Wy + (size_t)(kt * 64 + r) * 1024 + ncol0 + cc);
        }
        CP_COMMIT();
    };

    const int w = tid >> 5;
    const int wr = w >> 2, wc = w & 3;
    wmma::fragment<wmma::accumulator, 16, 16, 16, float> acc[4][2];
#pragma unroll
    for (int tr = 0; tr < 4; tr++)
#pragma unroll
        for (int n = 0; n < 2; n++) wmma::fill_fragment(acc[tr][n], 0.0f);

    load(0, 0);
    if (niter > 1) load(1, 1);
    int sidx = 0;
    for (int it = 0; it < niter; it++) {
        if (it + 1 < niter) CP_WAIT1(); else CP_WAIT0();
        __syncthreads();
        if (it + 2 < niter) load((sidx + 2) % 3, it + 2);
        const __half* Ab = smh + sidx * STAGE_H;
        const __half* Bb = smh + sidx * STAGE_H + 9216;
#pragma unroll
        for (int kk = 0; kk < 4; kk++) {
            wmma::fragment<wmma::matrix_b, 16, 16, 16, __half, wmma::row_major> fb[2];
#pragma unroll
            for (int n = 0; n < 2; n++)
                wmma::load_matrix_sync(fb[n], Bb + (kk * 16) * 136 + wc * 32 + n * 16, 136);
#pragma unroll
            for (int tr = 0; tr < 4; tr++) {
                wmma::fragment<wmma::matrix_a, 16, 16, 16, __half, wmma::row_major> fa;
                wmma::load_matrix_sync(fa, Ab + (wr * 64 + tr * 16) * 72 + kk * 16, 72);
#pragma unroll
                for (int n = 0; n < 2; n++)
                    wmma::mma_sync(acc[tr][n], fa, fb[n], acc[tr][n]);
            }
        }
        if (++sidx == 3) sidx = 0;
    }

#pragma unroll
    for (int tr = 0; tr < 4; tr++)
#pragma unroll
        for (int n = 0; n < 2; n++)
            wmma::store_matrix_sync(
                y + (size_t)(c0 + wr * 64 + tr * 16) * 1024 + ncol0 + wc * 32 + n * 16,
                acc[tr][n], 1024, wmma::mem_row_major);
}

// ---------------------------------------------------------------------------
extern "C" void kernel_launch(void* const* d_in, const int* in_sizes, int n_in,
                              void* d_out, int out_size) {
    const float* u  = (const float*)d_in[0];
    const float* x0 = (const float*)d_in[1];
    const float* A  = (const float*)d_in[2];
    const float* B  = (const float*)d_in[3];
    const float* C  = (const float*)d_in[4];
    const float* D  = (const float*)d_in[5];
    float* y = (float*)d_out;

    const int T  = in_sizes[0] / 64;     // 262144
    const int NC = T / 16;               // 16384
    const int NB = T * 64 / 2048;        // 8192 prepass blocks

    static bool attr_set = false;
    if (!attr_set) {
        cudaFuncSetAttribute(gemm1,  cudaFuncAttributeMaxDynamicSharedMemorySize, SMEM_3S);
        cudaFuncSetAttribute(stage2, cudaFuncAttributeMaxDynamicSharedMemorySize, SMEM_3S);
        attr_set = true;
    }

    prepass_fused<<<NB + 1, 256>>>(u, A, NB);
    setup_powers<<<64, 256>>>(B, C, D, x0);

    gemm1<<<(NC / 128) * 2, 256, SMEM_3S>>>();
    xs_epi<<<NC * 64 / 256, 256>>>();
    stage2<<<(NC / 128) * 8, 256, SMEM_3S>>>(y);
}

// round 7
// speedup vs baseline: 2.1158x; 1.0581x over previous
#include <cuda_runtime.h>
#include <cuda_fp16.h>
#include <mma.h>
#include <cstdint>

using namespace nvcuda;

// ---------------------------------------------------------------------------
// LinearRNN via two-stage chunked factorization (L=16, K=64 truncation).
//   Z  = Uc[16384x1024] @ Wf[1024x256]        (+ fused Xs epilogue)
//   Xs[c] = sum_b Z[c-4+b, 64b:64b+64] (+ A^{16c} x0 for c<4)
//   Y  = [Uc | Xs][16384x1088] @ Wy[1088x1024] (block-lower-triangular)
// 3 launches: [u-convert || full setup] -> [gemm1+Xs] -> [stage2].
// Setup blocks compute A^q locally (commuting squaring chain) -> no serial
// binpow dependency. gemm1 CTA pairs produce Z then the nt=1 CTA builds Xs
// after a flag spin (grid 256 <= 1 wave: all CTAs resident, deadlock-free).
// ---------------------------------------------------------------------------

#define STAGE_H 17920               // halves per pipeline stage (A 9216 + B 8704)
#define SMEM_3S (3 * STAGE_H * 2)   // 107520 bytes

// ------------------------- static device scratch ---------------------------
__device__ float  g_xfix[4 * 64];           // A^{16c} x0
__device__ __half g_Wf[1024 * 256];         // stage-1 weights
__device__ __half g_Wy[1088 * 1024];        // stage-2 weights
__device__ float  g_Z [16384 * 256];        // stage-1 partials
__device__ __half g_Xs[16384 * 64];         // chunk-start states
__device__ __half g_u16[262144 * 64];       // u in fp16
__device__ int    g_flag[128];              // gemm1 tile-pair completion

// ------------------------------ helpers ------------------------------------
__device__ __forceinline__ uint32_t smem_addr(const void* p) {
    return (uint32_t)__cvta_generic_to_shared(p);
}
#define CP16(dst, src) \
    asm volatile("cp.async.cg.shared.global [%0], [%1], 16;" :: "r"(dst), "l"(src))
#define CP_COMMIT() asm volatile("cp.async.commit_group;" ::: "memory")
#define CP_WAIT1()  asm volatile("cp.async.wait_group 1;" ::: "memory")
#define CP_WAIT0()  asm volatile("cp.async.wait_group 0;" ::: "memory")

__device__ __forceinline__ void mm_acc(const float* Sa, const float* Sb, int tid,
                                       float acc[4][4]) {
    int r0 = (tid >> 4) << 2, c0 = (tid & 15) << 2;
    for (int k = 0; k < 64; k++) {
        float4 b = *(const float4*)&Sb[k * 64 + c0];
#pragma unroll
        for (int i = 0; i < 4; i++) {
            float a = Sa[(r0 + i) * 64 + k];
            acc[i][0] += a * b.x; acc[i][1] += a * b.y;
            acc[i][2] += a * b.z; acc[i][3] += a * b.w;
        }
    }
}

// --------------- kernel 1: u conversion || full weight setup ----------------
// Blocks 0..63: setup for power q (local squaring chain; powers commute).
// Blocks 64..: stream-convert u fp32 -> fp16.
__global__ __launch_bounds__(256)
void fused_pre(const float* __restrict__ u,  const float* __restrict__ A,
               const float* __restrict__ Bm, const float* __restrict__ Cm,
               const float* __restrict__ Dm, const float* __restrict__ x0) {
    extern __shared__ float S[];                 // 4 x 4096 floats (64 KB)
    const int tid = threadIdx.x;

    if (blockIdx.x >= 64) {                      // ---- u conversion ----
        int idx = ((blockIdx.x - 64) * 256 + tid) * 8;
        float4 a = *(const float4*)(u + idx);
        float4 b = *(const float4*)(u + idx + 4);
        __half2 h0 = __floats2half2_rn(a.x, a.y), h1 = __floats2half2_rn(a.z, a.w);
        __half2 h2 = __floats2half2_rn(b.x, b.y), h3 = __floats2half2_rn(b.z, b.w);
        uint4 pk;
        pk.x = *(uint32_t*)&h0; pk.y = *(uint32_t*)&h1;
        pk.z = *(uint32_t*)&h2; pk.w = *(uint32_t*)&h3;
        *(uint4*)(g_u16 + idx) = pk;
        return;
    }

    // ---- setup block q ----
    const int q = blockIdx.x;
    const int r0 = (tid >> 4) << 2, c0 = (tid & 15) << 2;
    float* Sr = S;           float* Sp = S + 4096;     // P_q ping-pong
    float* cur = S + 8192;   float* spare = S + 12288; // A^(2^i) chain

    if (q == 0 && tid < 128) g_flag[tid] = 0;          // reset gemm1 flags

    for (int k = tid; k < 4096; k += 256) {
        cur[k] = A[k];
        Sr[k]  = ((k >> 6) == (k & 63)) ? 1.0f : 0.0f;
    }
    __syncthreads();

    for (int i = 0; i < 6; i++) {                      // P_q = prod A^(2^i)
        bool mul = (q >> i) & 1;
        bool sq  = (i < 5);
        float am[4][4] = {}, as[4][4] = {};
        if (mul) mm_acc(Sr, cur, tid, am);
        if (sq)  mm_acc(cur, cur, tid, as);
        if (mul) {
#pragma unroll
            for (int a2 = 0; a2 < 4; a2++)
#pragma unroll
                for (int b2 = 0; b2 < 4; b2++)
                    Sp[(r0 + a2) * 64 + c0 + b2] = am[a2][b2];
        }
        if (sq) {
#pragma unroll
            for (int a2 = 0; a2 < 4; a2++)
#pragma unroll
                for (int b2 = 0; b2 < 4; b2++)
                    spare[(r0 + a2) * 64 + c0 + b2] = as[a2][b2];
        }
        __syncthreads();
        if (mul) { float* t = Sr; Sr = Sp; Sp = t; }
        if (sq)  { float* t = cur; cur = spare; spare = t; }
    }

    float* Sf = cur;                                   // chain buffers dead
    // Mx_q = P_q @ B -> Sp
    for (int k = tid; k < 4096; k += 256) Sf[k] = Bm[k];
    __syncthreads();
    {
        float acc[4][4] = {};
        mm_acc(Sr, Sf, tid, acc);
        __syncthreads();                               // all reads of Sf done
#pragma unroll
        for (int a2 = 0; a2 < 4; a2++)
#pragma unroll
            for (int b2 = 0; b2 < 4; b2++)
                Sp[(r0 + a2) * 64 + c0 + b2] = acc[a2][b2];
    }
    __syncthreads();
    // Wf slot: q = 63-16b-r  ->  b=(63-q)>>4, r=(63-q)&15
    {
        int bb = (63 - q) >> 4, rr = (63 - q) & 15;
        for (int idx = tid; idx < 4096; idx += 256) {
            int j = idx >> 6, n = idx & 63;
            g_Wf[(size_t)(64 * rr + j) * 256 + 64 * bb + n] =
                __float2half_rn(Sp[n * 64 + j]);
        }
    }
    for (int k = tid; k < 4096; k += 256) Sf[k] = Cm[k];
    __syncthreads();
    if (q < 15) {  // Hp_{q+1} = C @ Mx_q -> blocks (s, s+q+1)
        float acc[4][4] = {};
        mm_acc(Sf, Sp, tid, acc);
        int m = q + 1;
        for (int s = 0; s + m < 16; s++) {
            int dt = s + m;
#pragma unroll
            for (int i2 = 0; i2 < 4; i2++)
#pragma unroll
                for (int j = 0; j < 4; j++)
                    g_Wy[(size_t)(64 * s + c0 + j) * 1024 + 64 * dt + r0 + i2] =
                        __float2half_rn(acc[i2][j]);
        }
    }
    if (q < 16) {  // G_q = C @ P_q (Xs rows) + D on diagonal
        float acc[4][4] = {};
        mm_acc(Sf, Sr, tid, acc);
#pragma unroll
        for (int i2 = 0; i2 < 4; i2++)
#pragma unroll
            for (int j = 0; j < 4; j++)
                g_Wy[(size_t)(1024 + c0 + j) * 1024 + 64 * q + r0 + i2] =
                    __float2half_rn(acc[i2][j]);
        for (int idx = tid; idx < 4096; idx += 256) {
            int p = idx >> 6, j = idx & 63;
            g_Wy[(size_t)(64 * q + j) * 1024 + 64 * q + p] = __float2half_rn(Dm[idx]);
        }
    }
    // zeros for dt < s
    for (int z = q; z < 120; z += 64) {
        int s = 1;
        while ((s * (s + 1)) / 2 <= z) s++;
        int dt = z - (s * (s - 1)) / 2;
        for (int idx = tid; idx < 4096; idx += 256) {
            int j = idx >> 6, p = idx & 63;
            g_Wy[(size_t)(64 * s + j) * 1024 + 64 * dt + p] = __half(0.0f);
        }
    }
    if ((q & 15) == 0 && tid < 64) {                   // xfix[c] = A^{16c} x0
        int c = q >> 4;
        float accx = 0.0f;
        for (int k = 0; k < 64; k++) accx += Sr[tid * 64 + k] * x0[k];
        g_xfix[c * 64 + tid] = accx;
    }
}

// ----------- kernel 2: Z = Uc @ Wf, fused Xs epilogue via flags -------------
__global__ __launch_bounds__(256, 2)
void gemm1() {
    extern __shared__ __half smh[];
    const int tid = threadIdx.x;
    const int mt = blockIdx.x >> 1, nt = blockIdx.x & 1;
    const int c0 = mt * 128, ncol0 = nt * 128;

    auto load = [&](int s, int kt) {
        __half* Ab = smh + s * STAGE_H;
        __half* Bb = smh + s * STAGE_H + 9216;
        for (int idx = tid; idx < 1024; idx += 256) {
            int i = idx >> 3, cc = (idx & 7) << 3;
            CP16(smem_addr(Ab + i * 72 + cc),
                 g_u16 + (size_t)(c0 + i) * 1024 + kt * 64 + cc);
        }
        for (int idx = tid; idx < 1024; idx += 256) {
            int r = idx >> 4, cc = (idx & 15) << 3;
            CP16(smem_addr(Bb + r * 136 + cc),
                 g_Wf + (size_t)(kt * 64 + r) * 256 + ncol0 + cc);
        }
        CP_COMMIT();
    };

    const int w = tid >> 5;
    const int wr = w >> 2, wc = w & 3;
    wmma::fragment<wmma::accumulator, 16, 16, 16, float> acc[4][2];
#pragma unroll
    for (int tr = 0; tr < 4; tr++)
#pragma unroll
        for (int n = 0; n < 2; n++) wmma::fill_fragment(acc[tr][n], 0.0f);

    load(0, 0);
    load(1, 1);
    int sidx = 0;
    for (int it = 0; it < 16; it++) {
        if (it + 1 < 16) CP_WAIT1(); else CP_WAIT0();
        __syncthreads();
        if (it + 2 < 16) load((sidx + 2) % 3, it + 2);
        const __half* Ab = smh + sidx * STAGE_H;
        const __half* Bb = smh + sidx * STAGE_H + 9216;
#pragma unroll
        for (int kk = 0; kk < 4; kk++) {
            wmma::fragment<wmma::matrix_b, 16, 16, 16, __half, wmma::row_major> fb[2];
#pragma unroll
            for (int n = 0; n < 2; n++)
                wmma::load_matrix_sync(fb[n], Bb + (kk * 16) * 136 + wc * 32 + n * 16, 136);
#pragma unroll
            for (int tr = 0; tr < 4; tr++) {
                wmma::fragment<wmma::matrix_a, 16, 16, 16, __half, wmma::row_major> fa;
                wmma::load_matrix_sync(fa, Ab + (wr * 64 + tr * 16) * 72 + kk * 16, 72);
#pragma unroll
                for (int n = 0; n < 2; n++)
                    wmma::mma_sync(acc[tr][n], fa, fb[n], acc[tr][n]);
            }
        }
        if (++sidx == 3) sidx = 0;
    }

#pragma unroll
    for (int tr = 0; tr < 4; tr++)
#pragma unroll
        for (int n = 0; n < 2; n++)
            wmma::store_matrix_sync(
                g_Z + (size_t)(c0 + wr * 64 + tr * 16) * 256 + ncol0 + wc * 32 + n * 16,
                acc[tr][n], 256, wmma::mem_row_major);

    // ---- fused Xs epilogue (flag handshake; grid=256 fits in one wave) ----
    __threadfence();
    __syncthreads();
    if (tid == 0) atomicAdd(&g_flag[mt], 1);
    if (nt == 1) {
        if (tid == 0) {
            while (*(volatile int*)&g_flag[mt] < 2) {}
            if (mt > 0) while (*(volatile int*)&g_flag[mt - 1] < 2) {}
        }
        __syncthreads();
        __threadfence();
        for (int idx = tid; idx < 8192; idx += 256) {
            int c = c0 + (idx >> 6), n = idx & 63;
            float v = (c < 4) ? g_xfix[c * 64 + n] : 0.0f;
#pragma unroll
            for (int b = 0; b < 4; b++) {
                int cp = c - 4 + b;
                if (cp >= 0) v += g_Z[(size_t)cp * 256 + 64 * b + n];
            }
            g_Xs[(size_t)c * 64 + n] = __float2half_rn(v);
        }
    }
}

// ------------------------------ stage 2 ------------------------------------
__global__ __launch_bounds__(256, 2)
void stage2(float* __restrict__ y) {
    extern __shared__ __half smh[];
    const int tid = threadIdx.x;
    const int mt = blockIdx.x >> 3, nt = blockIdx.x & 7;
    const int c0 = mt * 128, ncol0 = nt * 128;
    const int kmax = (2 * nt + 2 < 16) ? 2 * nt + 2 : 16;
    const int niter = kmax + 1;

    auto load = [&](int s, int i2) {
        int kt = (i2 == niter - 1) ? 16 : i2;
        __half* Ab = smh + s * STAGE_H;
        __half* Bb = smh + s * STAGE_H + 9216;
        for (int idx = tid; idx < 1024; idx += 256) {
            int i = idx >> 3, cc = (idx & 7) << 3;
            const __half* src = (kt < 16)
                ? g_u16 + (size_t)(c0 + i) * 1024 + kt * 64 + cc
                : g_Xs + (size_t)(c0 + i) * 64 + cc;
            CP16(smem_addr(Ab + i * 72 + cc), src);
        }
        for (int idx = tid; idx < 1024; idx += 256) {
            int r = idx >> 4, cc = (idx & 15) << 3;
            CP16(smem_addr(Bb + r * 136 + cc),
                 g_Wy + (size_t)(kt * 64 + r) * 1024 + ncol0 + cc);
        }
        CP_COMMIT();
    };

    const int w = tid >> 5;
    const int wr = w >> 2, wc = w & 3;
    wmma::fragment<wmma::accumulator, 16, 16, 16, float> acc[4][2];
#pragma unroll
    for (int tr = 0; tr < 4; tr++)
#pragma unroll
        for (int n = 0; n < 2; n++) wmma::fill_fragment(acc[tr][n], 0.0f);

    load(0, 0);
    if (niter > 1) load(1, 1);
    int sidx = 0;
    for (int it = 0; it < niter; it++) {
        if (it + 1 < niter) CP_WAIT1(); else CP_WAIT0();
        __syncthreads();
        if (it + 2 < niter) load((sidx + 2) % 3, it + 2);
        const __half* Ab = smh + sidx * STAGE_H;
        const __half* Bb = smh + sidx * STAGE_H + 9216;
#pragma unroll
        for (int kk = 0; kk < 4; kk++) {
            wmma::fragment<wmma::matrix_b, 16, 16, 16, __half, wmma::row_major> fb[2];
#pragma unroll
            for (int n = 0; n < 2; n++)
                wmma::load_matrix_sync(fb[n], Bb + (kk * 16) * 136 + wc * 32 + n * 16, 136);
#pragma unroll
            for (int tr = 0; tr < 4; tr++) {
                wmma::fragment<wmma::matrix_a, 16, 16, 16, __half, wmma::row_major> fa;
                wmma::load_matrix_sync(fa, Ab + (wr * 64 + tr * 16) * 72 + kk * 16, 72);
#pragma unroll
                for (int n = 0; n < 2; n++)
                    wmma::mma_sync(acc[tr][n], fa, fb[n], acc[tr][n]);
            }
        }
        if (++sidx == 3) sidx = 0;
    }

#pragma unroll
    for (int tr = 0; tr < 4; tr++)
#pragma unroll
        for (int n = 0; n < 2; n++)
            wmma::store_matrix_sync(
                y + (size_t)(c0 + wr * 64 + tr * 16) * 1024 + ncol0 + wc * 32 + n * 16,
                acc[tr][n], 1024, wmma::mem_row_major);
}

// ---------------------------------------------------------------------------
extern "C" void kernel_launch(void* const* d_in, const int* in_sizes, int n_in,
                              void* d_out, int out_size) {
    const float* u  = (const float*)d_in[0];
    const float* x0 = (const float*)d_in[1];
    const float* A  = (const float*)d_in[2];
    const float* B  = (const float*)d_in[3];
    const float* C  = (const float*)d_in[4];
    const float* D  = (const float*)d_in[5];
    float* y = (float*)d_out;

    const int T  = in_sizes[0] / 64;     // 262144
    const int NC = T / 16;               // 16384
    const int NB = T * 64 / 2048;        // 8192 conversion blocks

    static bool attr_set = false;
    if (!attr_set) {
        cudaFuncSetAttribute(fused_pre, cudaFuncAttributeMaxDynamicSharedMemorySize, 65536);
        cudaFuncSetAttribute(gemm1,  cudaFuncAttributeMaxDynamicSharedMemorySize, SMEM_3S);
        cudaFuncSetAttribute(stage2, cudaFuncAttributeMaxDynamicSharedMemorySize, SMEM_3S);
        attr_set = true;
    }

    fused_pre<<<64 + NB, 256, 65536>>>(u, A, B, C, D, x0);
    gemm1<<<(NC / 128) * 2, 256, SMEM_3S>>>();
    stage2<<<(NC / 128) * 8, 256, SMEM_3S>>>(y);
}